// round 1
// baseline (speedup 1.0000x reference)
#include <cuda_runtime.h>
#include <cuda_bf16.h>

// Problem: B=128 frames, N=16384 points (x,y,intensity), H=W=512 targets.
// out = mean over B*H*W of (bilinear_splat(points) - targets)^2
//
// Strategy: one CTA per (frame, 64-row strip). Rasterize the strip in
// 128 KB dynamic shared memory with shared atomics, then fuse the MSE
// reduction over the strip (targets read exactly once from DRAM).

constexpr int Bc = 128;
constexpr int Nc = 16384;
constexpr int Hc = 512;
constexpr int Wc = 512;
constexpr int ROWS = 64;                 // strip height
constexpr int STRIPS = Hc / ROWS;        // 8 strips per frame
constexpr int THREADS = 512;
constexpr int SMEM_BYTES = ROWS * Wc * 4;  // 131072 B

__global__ void zero_out_kernel(float* out) { *out = 0.0f; }

__global__ __launch_bounds__(THREADS, 1)
void splat_mse_kernel(const float* __restrict__ pts,
                      const float* __restrict__ tgt,
                      float* __restrict__ out) {
    extern __shared__ float img[];  // ROWS * Wc floats

    const int strip  = blockIdx.x % STRIPS;
    const int b      = blockIdx.x / STRIPS;
    const int y_base = strip * ROWS;
    const int tid    = threadIdx.x;

    // ---- zero the strip ----
    float4* img4 = reinterpret_cast<float4*>(img);
    #pragma unroll 4
    for (int i = tid; i < ROWS * Wc / 4; i += THREADS)
        img4[i] = make_float4(0.f, 0.f, 0.f, 0.f);
    __syncthreads();

    // ---- splat points of this frame that land in the strip ----
    const float* __restrict__ p = pts + (size_t)b * Nc * 3;
    const int y_end = y_base + ROWS;

    for (int i = tid; i < Nc; i += THREADS) {
        float x     = p[3 * i + 0];
        float y     = p[3 * i + 1];
        float inten = p[3 * i + 2];

        x = fminf(fmaxf(x, 0.0f), (float)(Wc - 1));
        y = fminf(fmaxf(y, 0.0f), (float)(Hc - 1));

        float x0f = floorf(x);
        float y0f = floorf(y);
        float fx  = x - x0f;
        float fy  = y - y0f;
        int x0 = (int)x0f;
        int y0 = (int)y0f;
        int x1 = min(x0 + 1, Wc - 1);
        int y1 = min(y0 + 1, Hc - 1);

        // rows touched: y0 and y1 = y0 or y0+1
        if (y1 < y_base || y0 >= y_end) continue;

        float wx0 = inten * (1.0f - fx);
        float wx1 = inten * fx;

        if (y0 >= y_base) {  // y0 < y_end guaranteed by reject above
            float wy = 1.0f - fy;
            int row = (y0 - y_base) * Wc;
            atomicAdd(&img[row + x0], wx0 * wy);
            atomicAdd(&img[row + x1], wx1 * wy);
        }
        if (y1 >= y_base && y1 < y_end) {
            int row = (y1 - y_base) * Wc;
            atomicAdd(&img[row + x0], wx0 * fy);
            atomicAdd(&img[row + x1], wx1 * fy);
        }
    }
    __syncthreads();

    // ---- fused MSE over the strip (targets read once, float4) ----
    const float4* __restrict__ t4 =
        reinterpret_cast<const float4*>(tgt + ((size_t)b * Hc + y_base) * Wc);

    float acc = 0.0f;
    #pragma unroll 4
    for (int i = tid; i < ROWS * Wc / 4; i += THREADS) {
        float4 tv = t4[i];
        float4 iv = img4[i];
        float d0 = iv.x - tv.x;
        float d1 = iv.y - tv.y;
        float d2 = iv.z - tv.z;
        float d3 = iv.w - tv.w;
        acc += d0 * d0 + d1 * d1 + d2 * d2 + d3 * d3;
    }

    // ---- block reduction ----
    #pragma unroll
    for (int off = 16; off > 0; off >>= 1)
        acc += __shfl_down_sync(0xFFFFFFFFu, acc, off);

    __shared__ float warp_sums[THREADS / 32];
    const int lane = tid & 31;
    const int wid  = tid >> 5;
    if (lane == 0) warp_sums[wid] = acc;
    __syncthreads();

    if (wid == 0) {
        float v = (lane < THREADS / 32) ? warp_sums[lane] : 0.0f;
        #pragma unroll
        for (int off = 8; off > 0; off >>= 1)
            v += __shfl_down_sync(0xFFFFFFFFu, v, off);
        if (lane == 0) {
            constexpr float INV_TOTAL =
                1.0f / ((float)Bc * (float)Hc * (float)Wc);
            atomicAdd(out, v * INV_TOTAL);
        }
    }
}

extern "C" void kernel_launch(void* const* d_in, const int* in_sizes, int n_in,
                              void* d_out, int out_size) {
    const float* pts = (const float*)d_in[0];   // [B, N, 3]
    const float* tgt = (const float*)d_in[1];   // [B, H, W]
    float* out = (float*)d_out;                 // scalar

    static bool attr_set = false;
    if (!attr_set) {
        cudaFuncSetAttribute(splat_mse_kernel,
                             cudaFuncAttributeMaxDynamicSharedMemorySize,
                             SMEM_BYTES);
        attr_set = true;
    }

    zero_out_kernel<<<1, 1>>>(out);
    splat_mse_kernel<<<Bc * STRIPS, THREADS, SMEM_BYTES>>>(pts, tgt, out);
}

// round 4
// speedup vs baseline: 2.2150x; 2.2150x over previous
#include <cuda_runtime.h>
#include <cuda_fp16.h>
#include <cuda_bf16.h>

// B=128 frames, N=16384 points (x,y,inten), H=W=512 targets.
// out = mean((bilinear_splat(points) - targets)^2)
//
// One CTA per (frame, 64-row strip). fp16 strip accumulator in 64 KB smem
// -> 3 CTAs/SM (75% occupancy). Points loaded 4-at-a-time via float4.

constexpr int Bc = 128;
constexpr int Nc = 16384;
constexpr int Hc = 512;
constexpr int Wc = 512;
constexpr int ROWS = 64;                   // strip height
constexpr int STRIPS = Hc / ROWS;          // 8
constexpr int THREADS = 512;
constexpr int SMEM_BYTES = ROWS * Wc * 2;  // 65536 B (half)

__global__ void zero_out_kernel(float* out) { *out = 0.0f; }

__device__ __forceinline__ void splat_point(
    __half* __restrict__ img, float x, float y, float inten,
    int y_base, int y_end)
{
    x = fminf(fmaxf(x, 0.0f), (float)(Wc - 1));
    y = fminf(fmaxf(y, 0.0f), (float)(Hc - 1));

    float x0f = floorf(x);
    float y0f = floorf(y);
    float fx  = x - x0f;
    float fy  = y - y0f;
    int x0 = (int)x0f;
    int y0 = (int)y0f;
    int x1 = min(x0 + 1, Wc - 1);
    int y1 = min(y0 + 1, Hc - 1);

    if (y1 < y_base || y0 >= y_end) return;

    float wx0 = inten * (1.0f - fx);
    float wx1 = inten * fx;

    if (y0 >= y_base) {
        float wy = 1.0f - fy;
        int row = (y0 - y_base) * Wc;
        atomicAdd(&img[row + x0], __float2half(wx0 * wy));
        atomicAdd(&img[row + x1], __float2half(wx1 * wy));
    }
    if (y1 >= y_base && y1 < y_end) {
        int row = (y1 - y_base) * Wc;
        atomicAdd(&img[row + x0], __float2half(wx0 * fy));
        atomicAdd(&img[row + x1], __float2half(wx1 * fy));
    }
}

__global__ __launch_bounds__(THREADS, 3)
void splat_mse_kernel(const float* __restrict__ pts,
                      const float* __restrict__ tgt,
                      float* __restrict__ out) {
    extern __shared__ __half img[];  // ROWS * Wc halves = 64 KB

    const int strip  = blockIdx.x % STRIPS;
    const int b      = blockIdx.x / STRIPS;
    const int y_base = strip * ROWS;
    const int y_end  = y_base + ROWS;
    const int tid    = threadIdx.x;

    // ---- zero the strip (uint4 = 8 halves) ----
    uint4* imgv = reinterpret_cast<uint4*>(img);
    constexpr int ZCHUNKS = ROWS * Wc / 8;  // 4096
    #pragma unroll
    for (int i = tid; i < ZCHUNKS; i += THREADS)
        imgv[i] = make_uint4(0u, 0u, 0u, 0u);
    __syncthreads();

    // ---- splat: 4 points per thread-iteration via 3 float4 loads ----
    const float4* __restrict__ p4 =
        reinterpret_cast<const float4*>(pts + (size_t)b * Nc * 3);
    constexpr int PITER = Nc / (THREADS * 4);  // 8

    #pragma unroll
    for (int it = 0; it < PITER; ++it) {
        int g = it * THREADS + tid;     // group of 4 points
        float4 a = p4[3 * g + 0];       // x0 y0 i0 x1
        float4 c = p4[3 * g + 1];       // y1 i1 x2 y2
        float4 d = p4[3 * g + 2];       // i2 x3 y3 i3

        splat_point(img, a.x, a.y, a.z, y_base, y_end);
        splat_point(img, a.w, c.x, c.y, y_base, y_end);
        splat_point(img, c.z, c.w, d.x, y_base, y_end);
        splat_point(img, d.y, d.z, d.w, y_base, y_end);
    }
    __syncthreads();

    // ---- fused MSE over the strip: 8 pixels / thread-iteration ----
    const float4* __restrict__ t4 =
        reinterpret_cast<const float4*>(tgt + ((size_t)b * Hc + y_base) * Wc);
    const __half2* __restrict__ img2 = reinterpret_cast<const __half2*>(img);

    float acc = 0.0f;
    constexpr int MCHUNKS = ROWS * Wc / 8;  // 4096
    #pragma unroll 4
    for (int i = tid; i < MCHUNKS; i += THREADS) {
        float4 tva = t4[2 * i + 0];
        float4 tvb = t4[2 * i + 1];
        float2 i0 = __half22float2(img2[4 * i + 0]);
        float2 i1 = __half22float2(img2[4 * i + 1]);
        float2 i2 = __half22float2(img2[4 * i + 2]);
        float2 i3 = __half22float2(img2[4 * i + 3]);

        float d0 = i0.x - tva.x;
        float d1 = i0.y - tva.y;
        float d2 = i1.x - tva.z;
        float d3 = i1.y - tva.w;
        float d4 = i2.x - tvb.x;
        float d5 = i2.y - tvb.y;
        float d6 = i3.x - tvb.z;
        float d7 = i3.y - tvb.w;
        acc += d0*d0 + d1*d1 + d2*d2 + d3*d3
             + d4*d4 + d5*d5 + d6*d6 + d7*d7;
    }

    // ---- block reduction ----
    #pragma unroll
    for (int off = 16; off > 0; off >>= 1)
        acc += __shfl_down_sync(0xFFFFFFFFu, acc, off);

    __shared__ float warp_sums[THREADS / 32];
    const int lane = tid & 31;
    const int wid  = tid >> 5;
    if (lane == 0) warp_sums[wid] = acc;
    __syncthreads();

    if (wid == 0) {
        float v = (lane < THREADS / 32) ? warp_sums[lane] : 0.0f;
        #pragma unroll
        for (int off = 8; off > 0; off >>= 1)
            v += __shfl_down_sync(0xFFFFFFFFu, v, off);
        if (lane == 0) {
            constexpr float INV_TOTAL =
                1.0f / ((float)Bc * (float)Hc * (float)Wc);
            atomicAdd(out, v * INV_TOTAL);
        }
    }
}

extern "C" void kernel_launch(void* const* d_in, const int* in_sizes, int n_in,
                              void* d_out, int out_size) {
    const float* pts = (const float*)d_in[0];   // [B, N, 3]
    const float* tgt = (const float*)d_in[1];   // [B, H, W]
    float* out = (float*)d_out;

    // Required for >48KB dynamic smem. Not a stream op -> legal during
    // graph capture; called unconditionally (no static guards).
    cudaFuncSetAttribute(splat_mse_kernel,
                         cudaFuncAttributeMaxDynamicSharedMemorySize,
                         SMEM_BYTES);

    zero_out_kernel<<<1, 1>>>(out);
    splat_mse_kernel<<<Bc * STRIPS, THREADS, SMEM_BYTES>>>(pts, tgt, out);
}